// round 5
// baseline (speedup 1.0000x reference)
#include <cuda_runtime.h>
#include <cuda_bf16.h>
#include <cstdint>
#include <math.h>

#define HID 128
#define MAXN 50000
#define MAXE 800000

typedef unsigned long long ull;

// ---------------- scratch (device globals) ----------------
__device__ int   g_counts[MAXN + 1];
__device__ int   g_off[MAXN + 1];
__device__ int   g_cursor[MAXN];
__device__ int   g_esrc[MAXE];
__device__ float g_aggr[(size_t)MAXN * HID];
__device__ float g_h1[(size_t)MAXN * HID];
__device__ float g_h2[(size_t)MAXN * HID];

// ---------------- f32x2 packed-math macros ----------------
#define PACKF2(out, lo, hi) \
    asm("mov.b64 %0, {%1, %2};" : "=l"(out) : "f"(lo), "f"(hi))
#define UNPACKF2(lo, hi, v) \
    asm("mov.b64 {%0, %1}, %2;" : "=f"(lo), "=f"(hi) : "l"(v))
#define FMAF2(acc, a, b) \
    asm("fma.rn.f32x2 %0, %1, %2, %0;" : "+l"(acc) : "l"(a), "l"(b))

// ---------------- CSR build ----------------
__global__ void zero_int_kernel(int* __restrict__ p, int n) {
    int i = blockIdx.x * blockDim.x + threadIdx.x;
    if (i < n) p[i] = 0;
}

__global__ void hist_kernel(const int* __restrict__ dst, int* __restrict__ counts, int E) {
    int e = blockIdx.x * blockDim.x + threadIdx.x;
    if (e < E) atomicAdd(&counts[dst[e]], 1);
}

__global__ void scan_kernel(const int* __restrict__ counts, int* __restrict__ off,
                            int* __restrict__ cursor, int n) {
    __shared__ int part[1024];
    int tid = threadIdx.x;
    int chunk = (n + 1023) >> 10;
    int start = tid * chunk;
    int end = start + chunk; if (end > n) end = n;
    int s = 0;
    for (int i = start; i < end; i++) s += counts[i];
    part[tid] = s;
    __syncthreads();
    for (int d = 1; d < 1024; d <<= 1) {
        int v = (tid >= d) ? part[tid - d] : 0;
        __syncthreads();
        part[tid] += v;
        __syncthreads();
    }
    int pre = (tid == 0) ? 0 : part[tid - 1];
    for (int i = start; i < end; i++) {
        off[i] = pre;
        cursor[i] = pre;
        pre += counts[i];
    }
    if (end == n) off[n] = pre;
}

__global__ void fill_kernel(const int* __restrict__ src, const int* __restrict__ dst,
                            int* __restrict__ cursor, int* __restrict__ esrc, int E) {
    int e = blockIdx.x * blockDim.x + threadIdx.x;
    if (e < E) {
        int d = dst[e];
        int pos = atomicAdd(&cursor[d], 1);
        esrc[pos] = src[e];
    }
}

// ---------------- gather-aggregate (mean): warp per dst node ----------------
__global__ void gather_kernel(const float* __restrict__ feat, const int* __restrict__ esrc,
                              const int* __restrict__ off, float* __restrict__ aggr, int n) {
    int w = (blockIdx.x * blockDim.x + threadIdx.x) >> 5;
    int lane = threadIdx.x & 31;
    if (w >= n) return;
    int o0 = off[w], o1 = off[w + 1];
    const float4* f4 = (const float4*)feat;
    float4 a0 = {0.f, 0.f, 0.f, 0.f};
    float4 a1 = {0.f, 0.f, 0.f, 0.f};
    int k = o0;
    for (; k + 2 <= o1; k += 2) {
        int s0 = __ldg(esrc + k);
        int s1 = __ldg(esrc + k + 1);
        float4 v0 = f4[(size_t)s0 * 32 + lane];
        float4 v1 = f4[(size_t)s1 * 32 + lane];
        a0.x += v0.x; a0.y += v0.y; a0.z += v0.z; a0.w += v0.w;
        a1.x += v1.x; a1.y += v1.y; a1.z += v1.z; a1.w += v1.w;
    }
    if (k < o1) {
        int s = __ldg(esrc + k);
        float4 v = f4[(size_t)s * 32 + lane];
        a0.x += v.x; a0.y += v.y; a0.z += v.z; a0.w += v.w;
    }
    float inv = 1.0f / fmaxf((float)(o1 - o0), 1.0f);
    float4 r;
    r.x = (a0.x + a1.x) * inv;
    r.y = (a0.y + a1.y) * inv;
    r.z = (a0.z + a1.z) * inv;
    r.w = (a0.w + a1.w) * inv;
    ((float4*)aggr)[(size_t)w * 32 + lane] = r;
}

// ---------------- register-blocked f32x2 SAGE layer ----------------
// out[node][c] = relu( sum_k S[node][k] * W[k][c] + b[c] ),  S=[A|X], W=[Wl;Wr], K=256.
// Block: 128 threads = 16 node-groups x 8 col-groups. Thread tile: 8 nodes x 16 cols
// (64 f32x2 accumulators, pair = adjacent cols). Per k: 8 LDS64 A-dup (broadcast) +
// 8 LDS64 W col-pairs = 128B feeding 128 FMA-lanes -> fma-pipe + LDS both at roofline.
// smem: W[256][128] f32 (128KB) + S-dup chunk [64][128] f32x2 (64KB) + bias.
#define KCHUNK 64
#define SM_W_OFF 512
#define SM_S_OFF (512 + 256 * 128 * 4)
#define LAYER_SMEM (512 + 256 * 128 * 4 + KCHUNK * 128 * 8)

__global__ void __launch_bounds__(128, 1)
layer_kernel(const float* __restrict__ A, const float* __restrict__ X,
             const float* __restrict__ Wl, const float* __restrict__ Wr,
             const float* __restrict__ bias, float* __restrict__ out, int n) {
    extern __shared__ char smem[];
    float* sBias = (float*)smem;
    float* sW = (float*)(smem + SM_W_OFF);        // [256][128]
    ull*   sS = (ull*)(smem + SM_S_OFF);          // [KCHUNK][128] dup pairs

    int tid = threadIdx.x;
    int cg = tid & 7;          // col-group: cols cg*16 .. +16
    int ng = tid >> 3;         // node-group: nodes ng*8 .. +8
    int c0 = cg * 16;
    int n0loc = ng * 8;

    // stage W = [Wl;Wr] and bias (once per block)
    {
        const float4* wl4 = (const float4*)Wl;
        const float4* wr4 = (const float4*)Wr;
        float4* sW4 = (float4*)sW;
        #pragma unroll
        for (int q = 0; q < 32; q++) {           // 128 threads * 32 * 16B = 64KB
            sW4[q * 128 + tid] = wl4[q * 128 + tid];
            sW4[4096 + q * 128 + tid] = wr4[q * 128 + tid];
        }
        if (tid < 128) sBias[tid] = bias[tid];
    }

    int nTiles = (n + 127) >> 7;
    for (int tile = blockIdx.x; tile < nTiles; tile += gridDim.x) {
        int myNode = tile * 128 + tid;           // staging: thread -> one node row
        bool sValid = myNode < n;

        ull acc[8][8];
        #pragma unroll
        for (int i = 0; i < 8; i++)
            #pragma unroll
            for (int j = 0; j < 8; j++) acc[i][j] = 0ull;

        for (int kc = 0; kc < 4; kc++) {
            __syncthreads();   // protect sS reuse (and sW on first iter)
            // stage S-dup chunk: this thread's node row, 64 k values duplicated
            {
                const float* srcrow = (kc < 2)
                    ? (A + (size_t)myNode * HID + kc * 64)
                    : (X + (size_t)myNode * HID + (kc - 2) * 64);
                const float4* s4 = (const float4*)srcrow;
                #pragma unroll
                for (int q = 0; q < 16; q++) {
                    float4 v;
                    if (sValid) v = s4[q];
                    else v = make_float4(0.f, 0.f, 0.f, 0.f);
                    ull d0, d1, d2, d3;
                    PACKF2(d0, v.x, v.x);
                    PACKF2(d1, v.y, v.y);
                    PACKF2(d2, v.z, v.z);
                    PACKF2(d3, v.w, v.w);
                    int kl = q * 4;
                    sS[(kl + 0) * 128 + tid] = d0;
                    sS[(kl + 1) * 128 + tid] = d1;
                    sS[(kl + 2) * 128 + tid] = d2;
                    sS[(kl + 3) * 128 + tid] = d3;
                }
            }
            __syncthreads();

            const float* wbase = sW + (size_t)kc * KCHUNK * 128 + c0;
            #pragma unroll 2
            for (int k = 0; k < KCHUNK; k++) {
                ull a2[8], w2[8];
                const ull* srow = sS + k * 128 + n0loc;
                const ull* wrow = (const ull*)(wbase + k * 128);
                #pragma unroll
                for (int i = 0; i < 8; i++) a2[i] = srow[i];
                #pragma unroll
                for (int j = 0; j < 8; j++) w2[j] = wrow[j];
                #pragma unroll
                for (int i = 0; i < 8; i++)
                    #pragma unroll
                    for (int j = 0; j < 8; j++)
                        FMAF2(acc[i][j], a2[i], w2[j]);
            }
        }

        // epilogue: bias + relu + store (8 nodes x 16 cols per thread)
        #pragma unroll
        for (int i = 0; i < 8; i++) {
            int node = tile * 128 + n0loc + i;
            if (node >= n) break;
            float* po = out + (size_t)node * HID + c0;
            #pragma unroll
            for (int j = 0; j < 8; j += 2) {
                float v0, v1, v2, v3;
                UNPACKF2(v0, v1, acc[i][j]);
                UNPACKF2(v2, v3, acc[i][j + 1]);
                float4 o;
                o.x = fmaxf(v0 + sBias[c0 + j * 2 + 0], 0.f);
                o.y = fmaxf(v1 + sBias[c0 + j * 2 + 1], 0.f);
                o.z = fmaxf(v2 + sBias[c0 + j * 2 + 2], 0.f);
                o.w = fmaxf(v3 + sBias[c0 + j * 2 + 3], 0.f);
                *(float4*)(po + j * 2) = o;
            }
        }
    }
}

// ---------------- logits head: warp per node ----------------
__global__ void logits_kernel(const float* __restrict__ h, const float* __restrict__ Wout,
                              const float* __restrict__ bout, float* __restrict__ out, int n) {
    int w = (blockIdx.x * blockDim.x + threadIdx.x) >> 5;
    int lane = threadIdx.x & 31;
    if (w >= n) return;
    float4 v = ((const float4*)(h + (size_t)w * HID))[lane];
    int k = lane * 4;
    float s0 = v.x * Wout[(k + 0) * 2 + 0] + v.y * Wout[(k + 1) * 2 + 0] +
               v.z * Wout[(k + 2) * 2 + 0] + v.w * Wout[(k + 3) * 2 + 0];
    float s1 = v.x * Wout[(k + 0) * 2 + 1] + v.y * Wout[(k + 1) * 2 + 1] +
               v.z * Wout[(k + 2) * 2 + 1] + v.w * Wout[(k + 3) * 2 + 1];
    #pragma unroll
    for (int off = 16; off > 0; off >>= 1) {
        s0 += __shfl_xor_sync(0xFFFFFFFFu, s0, off);
        s1 += __shfl_xor_sync(0xFFFFFFFFu, s1, off);
    }
    if (lane == 0) {
        out[(size_t)w * 2 + 0] = s0 + bout[0];
        out[(size_t)w * 2 + 1] = s1 + bout[1];
    }
}

// ---------------- launch ----------------
extern "C" void kernel_launch(void* const* d_in, const int* in_sizes, int n_in,
                              void* d_out, int out_size) {
    const float* x    = (const float*)d_in[0];
    const int*   ei   = (const int*)d_in[1];   // int32 on device
    const float* W1l  = (const float*)d_in[2];
    const float* W1r  = (const float*)d_in[3];
    const float* b1   = (const float*)d_in[4];
    const float* W2l  = (const float*)d_in[5];
    const float* W2r  = (const float*)d_in[6];
    const float* b2   = (const float*)d_in[7];
    const float* Wout = (const float*)d_in[8];
    const float* bout = (const float*)d_in[9];
    float* dout = (float*)d_out;

    int n = in_sizes[0] / HID;
    int E = in_sizes[1] / 2;
    const int* src = ei;
    const int* dst = ei + E;

    int *p_counts, *p_off, *p_cursor, *p_esrc;
    float *p_aggr, *p_h1, *p_h2;
    cudaGetSymbolAddress((void**)&p_counts, g_counts);
    cudaGetSymbolAddress((void**)&p_off,    g_off);
    cudaGetSymbolAddress((void**)&p_cursor, g_cursor);
    cudaGetSymbolAddress((void**)&p_esrc,   g_esrc);
    cudaGetSymbolAddress((void**)&p_aggr,   g_aggr);
    cudaGetSymbolAddress((void**)&p_h1,     g_h1);
    cudaGetSymbolAddress((void**)&p_h2,     g_h2);

    cudaFuncSetAttribute(layer_kernel, cudaFuncAttributeMaxDynamicSharedMemorySize, LAYER_SMEM);

    // tuple output: logits [n*2] then h [n*128]
    float* hOut = ((size_t)out_size >= (size_t)n * (HID + 2)) ? (dout + (size_t)n * 2) : p_h2;

    // ---- CSR build ----
    zero_int_kernel<<<(n + 255) / 256, 256>>>(p_counts, n);
    hist_kernel<<<(E + 255) / 256, 256>>>(dst, p_counts, E);
    scan_kernel<<<1, 1024>>>(p_counts, p_off, p_cursor, n);
    fill_kernel<<<(E + 255) / 256, 256>>>(src, dst, p_cursor, p_esrc, E);

    int gatherGrid = (n * 32 + 255) / 256;
    int nTiles = (n + 127) >> 7;
    int layerGrid = nTiles < 148 ? nTiles : 148;

    // ---- layer 1 ----
    gather_kernel<<<gatherGrid, 256>>>(x, p_esrc, p_off, p_aggr, n);
    layer_kernel<<<layerGrid, 128, LAYER_SMEM>>>(p_aggr, x, W1l, W1r, b1, p_h1, n);

    // ---- layer 2 ----
    gather_kernel<<<gatherGrid, 256>>>(p_h1, p_esrc, p_off, p_aggr, n);
    layer_kernel<<<layerGrid, 128, LAYER_SMEM>>>(p_aggr, p_h1, W2l, W2r, b2, hOut, n);

    // ---- head ----
    logits_kernel<<<(n * 32 + 255) / 256, 256>>>(hOut, Wout, bout, dout, n);
}

// round 6
// speedup vs baseline: 1.3260x; 1.3260x over previous
#include <cuda_runtime.h>
#include <cuda_bf16.h>
#include <cstdint>
#include <math.h>

#define HID 128
#define MAXN 50000
#define MAXE 800000

typedef unsigned long long ull;

// ---------------- scratch (device globals) ----------------
__device__ int   g_counts[MAXN + 1];
__device__ int   g_off[MAXN + 1];
__device__ int   g_cursor[MAXN];
__device__ int   g_esrc[MAXE];
__device__ float g_aggr[(size_t)MAXN * HID];
__device__ float g_h1[(size_t)MAXN * HID];
__device__ float g_h2[(size_t)MAXN * HID];

// ---------------- f32x2 packed-math macros ----------------
#define PACKF2(out, lo, hi) \
    asm("mov.b64 %0, {%1, %2};" : "=l"(out) : "f"(lo), "f"(hi))
#define UNPACKF2(lo, hi, v) \
    asm("mov.b64 {%0, %1}, %2;" : "=f"(lo), "=f"(hi) : "l"(v))
#define FMAF2(acc, a, b) \
    asm("fma.rn.f32x2 %0, %1, %2, %0;" : "+l"(acc) : "l"(a), "l"(b))

// ---------------- CSR build ----------------
__global__ void zero_int_kernel(int* __restrict__ p, int n) {
    int i = blockIdx.x * blockDim.x + threadIdx.x;
    if (i < n) p[i] = 0;
}

__global__ void hist_kernel(const int* __restrict__ dst, int* __restrict__ counts, int E) {
    int e = blockIdx.x * blockDim.x + threadIdx.x;
    if (e < E) atomicAdd(&counts[dst[e]], 1);
}

__global__ void scan_kernel(const int* __restrict__ counts, int* __restrict__ off,
                            int* __restrict__ cursor, int n) {
    __shared__ int part[1024];
    int tid = threadIdx.x;
    int chunk = (n + 1023) >> 10;
    int start = tid * chunk;
    int end = start + chunk; if (end > n) end = n;
    int s = 0;
    for (int i = start; i < end; i++) s += counts[i];
    part[tid] = s;
    __syncthreads();
    for (int d = 1; d < 1024; d <<= 1) {
        int v = (tid >= d) ? part[tid - d] : 0;
        __syncthreads();
        part[tid] += v;
        __syncthreads();
    }
    int pre = (tid == 0) ? 0 : part[tid - 1];
    for (int i = start; i < end; i++) {
        off[i] = pre;
        cursor[i] = pre;
        pre += counts[i];
    }
    if (end == n) off[n] = pre;
}

__global__ void fill_kernel(const int* __restrict__ src, const int* __restrict__ dst,
                            int* __restrict__ cursor, int* __restrict__ esrc, int E) {
    int e = blockIdx.x * blockDim.x + threadIdx.x;
    if (e < E) {
        int d = dst[e];
        int pos = atomicAdd(&cursor[d], 1);
        esrc[pos] = src[e];
    }
}

// ---------------- gather-aggregate (mean): warp per dst node, MLP=4 ----------------
__global__ void gather_kernel(const float* __restrict__ feat, const int* __restrict__ esrc,
                              const int* __restrict__ off, float* __restrict__ aggr, int n) {
    int w = (blockIdx.x * blockDim.x + threadIdx.x) >> 5;
    int lane = threadIdx.x & 31;
    if (w >= n) return;
    int o0 = off[w], o1 = off[w + 1];
    const float4* f4 = (const float4*)feat;
    float4 a0 = {0.f, 0.f, 0.f, 0.f};
    float4 a1 = {0.f, 0.f, 0.f, 0.f};
    int k = o0;
    for (; k + 4 <= o1; k += 4) {
        int s0 = __ldg(esrc + k);
        int s1 = __ldg(esrc + k + 1);
        int s2 = __ldg(esrc + k + 2);
        int s3 = __ldg(esrc + k + 3);
        float4 v0 = f4[(size_t)s0 * 32 + lane];
        float4 v1 = f4[(size_t)s1 * 32 + lane];
        float4 v2 = f4[(size_t)s2 * 32 + lane];
        float4 v3 = f4[(size_t)s3 * 32 + lane];
        a0.x += v0.x; a0.y += v0.y; a0.z += v0.z; a0.w += v0.w;
        a1.x += v1.x; a1.y += v1.y; a1.z += v1.z; a1.w += v1.w;
        a0.x += v2.x; a0.y += v2.y; a0.z += v2.z; a0.w += v2.w;
        a1.x += v3.x; a1.y += v3.y; a1.z += v3.z; a1.w += v3.w;
    }
    for (; k < o1; k++) {
        int s = __ldg(esrc + k);
        float4 v = f4[(size_t)s * 32 + lane];
        a0.x += v.x; a0.y += v.y; a0.z += v.z; a0.w += v.w;
    }
    float inv = 1.0f / fmaxf((float)(o1 - o0), 1.0f);
    float4 r;
    r.x = (a0.x + a1.x) * inv;
    r.y = (a0.y + a1.y) * inv;
    r.z = (a0.z + a1.z) * inv;
    r.w = (a0.w + a1.w) * inv;
    ((float4*)aggr)[(size_t)w * 32 + lane] = r;
}

// ---------------- register-blocked f32x2 SAGE layer (v3) ----------------
// out[node][col] = relu( sum_k S[node][k]*W[k][col] + b[col] ), S=[A|X], W=[Wl;Wr], K=256.
// 256 threads: c = tid&15 (cols [8c,8c+8)), ng = tid>>4 (nodes [8ng,8ng+8)).
// Thread tile 8 nodes x 8 cols = 32 FFMA2/k from 12 LDS64/k -> fma-pipe-bound.
// sW[k][j*16+c] = pack(W[k][8c+2j], W[k][8c+2j+1])  (transposed pairs: warp reads 128B contig)
// sS[k][node] = pack(s, s) duplicated, row stride 129 ull (pad kills STS 16-way conflict)
#define KCH 64
#define SROW 129
#define SM_BIAS 0
#define SM_W 512
#define SM_S (512 + 256 * 64 * 8)
#define LAYER_SMEM (SM_S + KCH * SROW * 8)

__global__ void __launch_bounds__(256, 1)
layer_kernel(const float* __restrict__ A, const float* __restrict__ X,
             const float* __restrict__ Wl, const float* __restrict__ Wr,
             const float* __restrict__ bias, float* __restrict__ out, int n) {
    extern __shared__ char smem[];
    float* sBias = (float*)(smem + SM_BIAS);
    ull* sW = (ull*)(smem + SM_W);   // [256][64]
    ull* sS = (ull*)(smem + SM_S);   // [KCH][SROW]

    int tid = threadIdx.x;
    int c  = tid & 15;
    int ng = tid >> 4;

    // stage W (transposed pair layout) + bias, once per block
    for (int idx = tid; idx < 256 * 64; idx += 256) {
        int k = idx >> 6, p = idx & 63;
        int cc = p >> 2, j = p & 3;
        const float* wsrc = (k < 128) ? (Wl + (size_t)k * 128) : (Wr + (size_t)(k - 128) * 128);
        float w0 = wsrc[2 * p];
        float w1 = wsrc[2 * p + 1];
        ull wp;
        PACKF2(wp, w0, w1);
        sW[k * 64 + j * 16 + cc] = wp;
    }
    if (tid < 128) sBias[tid] = bias[tid];

    int nTiles = (n + 127) >> 7;
    for (int tile = blockIdx.x; tile < nTiles; tile += gridDim.x) {
        ull acc[8][4];
        #pragma unroll
        for (int i = 0; i < 8; i++)
            #pragma unroll
            for (int j = 0; j < 4; j++) acc[i][j] = 0ull;

        #pragma unroll
        for (int kc = 0; kc < 4; kc++) {
            __syncthreads();   // protects sS reuse (and sW/bias on first pass)
            // stage S chunk: 8 passes, warp reads 2 rows x 256B (coalesced)
            {
                int q = tid & 15;          // float4 index within 64-k chunk
                int nl0 = tid >> 4;        // 0..15
                const float* base = (kc < 2) ? A : X;
                int kbase = (kc & 1) * 64;
                #pragma unroll
                for (int pass = 0; pass < 8; pass++) {
                    int nodeLoc = pass * 16 + nl0;
                    int node = tile * 128 + nodeLoc;
                    float4 v;
                    if (node < n) v = *(const float4*)(base + (size_t)node * HID + kbase + q * 4);
                    else v = make_float4(0.f, 0.f, 0.f, 0.f);
                    ull d0, d1, d2, d3;
                    PACKF2(d0, v.x, v.x);
                    PACKF2(d1, v.y, v.y);
                    PACKF2(d2, v.z, v.z);
                    PACKF2(d3, v.w, v.w);
                    int kl = q * 4;
                    sS[(kl + 0) * SROW + nodeLoc] = d0;
                    sS[(kl + 1) * SROW + nodeLoc] = d1;
                    sS[(kl + 2) * SROW + nodeLoc] = d2;
                    sS[(kl + 3) * SROW + nodeLoc] = d3;
                }
            }
            __syncthreads();

            const ull* wbase = sW + (size_t)kc * 64 * 64 + c;
            #pragma unroll 2
            for (int k = 0; k < KCH; k++) {
                const ull* srow = sS + k * SROW + ng * 8;
                const ull* wrow = wbase + k * 64;
                ull a0 = srow[0], a1 = srow[1], a2 = srow[2], a3 = srow[3];
                ull a4 = srow[4], a5 = srow[5], a6 = srow[6], a7 = srow[7];
                ull w0 = wrow[0], w1 = wrow[16], w2 = wrow[32], w3 = wrow[48];
                FMAF2(acc[0][0], a0, w0); FMAF2(acc[0][1], a0, w1);
                FMAF2(acc[0][2], a0, w2); FMAF2(acc[0][3], a0, w3);
                FMAF2(acc[1][0], a1, w0); FMAF2(acc[1][1], a1, w1);
                FMAF2(acc[1][2], a1, w2); FMAF2(acc[1][3], a1, w3);
                FMAF2(acc[2][0], a2, w0); FMAF2(acc[2][1], a2, w1);
                FMAF2(acc[2][2], a2, w2); FMAF2(acc[2][3], a2, w3);
                FMAF2(acc[3][0], a3, w0); FMAF2(acc[3][1], a3, w1);
                FMAF2(acc[3][2], a3, w2); FMAF2(acc[3][3], a3, w3);
                FMAF2(acc[4][0], a4, w0); FMAF2(acc[4][1], a4, w1);
                FMAF2(acc[4][2], a4, w2); FMAF2(acc[4][3], a4, w3);
                FMAF2(acc[5][0], a5, w0); FMAF2(acc[5][1], a5, w1);
                FMAF2(acc[5][2], a5, w2); FMAF2(acc[5][3], a5, w3);
                FMAF2(acc[6][0], a6, w0); FMAF2(acc[6][1], a6, w1);
                FMAF2(acc[6][2], a6, w2); FMAF2(acc[6][3], a6, w3);
                FMAF2(acc[7][0], a7, w0); FMAF2(acc[7][1], a7, w1);
                FMAF2(acc[7][2], a7, w2); FMAF2(acc[7][3], a7, w3);
            }
        }

        // epilogue: bias + relu + store. Thread covers nodes [8ng,8ng+8) x cols [8c,8c+8).
        // col pair j holds cols (8c+2j, 8c+2j+1).
        #pragma unroll
        for (int i = 0; i < 8; i++) {
            int node = tile * 128 + ng * 8 + i;
            if (node >= n) break;
            float* po = out + (size_t)node * HID + c * 8;
            float v0, v1, v2, v3;
            UNPACKF2(v0, v1, acc[i][0]);
            UNPACKF2(v2, v3, acc[i][1]);
            float4 o;
            o.x = fmaxf(v0 + sBias[c * 8 + 0], 0.f);
            o.y = fmaxf(v1 + sBias[c * 8 + 1], 0.f);
            o.z = fmaxf(v2 + sBias[c * 8 + 2], 0.f);
            o.w = fmaxf(v3 + sBias[c * 8 + 3], 0.f);
            *(float4*)po = o;
            UNPACKF2(v0, v1, acc[i][2]);
            UNPACKF2(v2, v3, acc[i][3]);
            o.x = fmaxf(v0 + sBias[c * 8 + 4], 0.f);
            o.y = fmaxf(v1 + sBias[c * 8 + 5], 0.f);
            o.z = fmaxf(v2 + sBias[c * 8 + 6], 0.f);
            o.w = fmaxf(v3 + sBias[c * 8 + 7], 0.f);
            *(float4*)(po + 4) = o;
        }
    }
}

// ---------------- logits head: warp per node ----------------
__global__ void logits_kernel(const float* __restrict__ h, const float* __restrict__ Wout,
                              const float* __restrict__ bout, float* __restrict__ out, int n) {
    int w = (blockIdx.x * blockDim.x + threadIdx.x) >> 5;
    int lane = threadIdx.x & 31;
    if (w >= n) return;
    float4 v = ((const float4*)(h + (size_t)w * HID))[lane];
    int k = lane * 4;
    float s0 = v.x * Wout[(k + 0) * 2 + 0] + v.y * Wout[(k + 1) * 2 + 0] +
               v.z * Wout[(k + 2) * 2 + 0] + v.w * Wout[(k + 3) * 2 + 0];
    float s1 = v.x * Wout[(k + 0) * 2 + 1] + v.y * Wout[(k + 1) * 2 + 1] +
               v.z * Wout[(k + 2) * 2 + 1] + v.w * Wout[(k + 3) * 2 + 1];
    #pragma unroll
    for (int off = 16; off > 0; off >>= 1) {
        s0 += __shfl_xor_sync(0xFFFFFFFFu, s0, off);
        s1 += __shfl_xor_sync(0xFFFFFFFFu, s1, off);
    }
    if (lane == 0) {
        out[(size_t)w * 2 + 0] = s0 + bout[0];
        out[(size_t)w * 2 + 1] = s1 + bout[1];
    }
}

// ---------------- launch ----------------
extern "C" void kernel_launch(void* const* d_in, const int* in_sizes, int n_in,
                              void* d_out, int out_size) {
    const float* x    = (const float*)d_in[0];
    const int*   ei   = (const int*)d_in[1];   // int32 on device
    const float* W1l  = (const float*)d_in[2];
    const float* W1r  = (const float*)d_in[3];
    const float* b1   = (const float*)d_in[4];
    const float* W2l  = (const float*)d_in[5];
    const float* W2r  = (const float*)d_in[6];
    const float* b2   = (const float*)d_in[7];
    const float* Wout = (const float*)d_in[8];
    const float* bout = (const float*)d_in[9];
    float* dout = (float*)d_out;

    int n = in_sizes[0] / HID;
    int E = in_sizes[1] / 2;
    const int* src = ei;
    const int* dst = ei + E;

    int *p_counts, *p_off, *p_cursor, *p_esrc;
    float *p_aggr, *p_h1, *p_h2;
    cudaGetSymbolAddress((void**)&p_counts, g_counts);
    cudaGetSymbolAddress((void**)&p_off,    g_off);
    cudaGetSymbolAddress((void**)&p_cursor, g_cursor);
    cudaGetSymbolAddress((void**)&p_esrc,   g_esrc);
    cudaGetSymbolAddress((void**)&p_aggr,   g_aggr);
    cudaGetSymbolAddress((void**)&p_h1,     g_h1);
    cudaGetSymbolAddress((void**)&p_h2,     g_h2);

    cudaFuncSetAttribute(layer_kernel, cudaFuncAttributeMaxDynamicSharedMemorySize, LAYER_SMEM);

    // tuple output: logits [n*2] then h [n*128]
    float* hOut = ((size_t)out_size >= (size_t)n * (HID + 2)) ? (dout + (size_t)n * 2) : p_h2;

    // ---- CSR build ----
    zero_int_kernel<<<(n + 255) / 256, 256>>>(p_counts, n);
    hist_kernel<<<(E + 255) / 256, 256>>>(dst, p_counts, E);
    scan_kernel<<<1, 1024>>>(p_counts, p_off, p_cursor, n);
    fill_kernel<<<(E + 255) / 256, 256>>>(src, dst, p_cursor, p_esrc, E);

    int gatherGrid = (n * 32 + 255) / 256;
    int nTiles = (n + 127) >> 7;
    int layerGrid = nTiles < 148 ? nTiles : 148;

    // ---- layer 1 ----
    gather_kernel<<<gatherGrid, 256>>>(x, p_esrc, p_off, p_aggr, n);
    layer_kernel<<<layerGrid, 256, LAYER_SMEM>>>(p_aggr, x, W1l, W1r, b1, p_h1, n);

    // ---- layer 2 ----
    gather_kernel<<<gatherGrid, 256>>>(p_h1, p_esrc, p_off, p_aggr, n);
    layer_kernel<<<layerGrid, 256, LAYER_SMEM>>>(p_aggr, p_h1, W2l, W2r, b2, hOut, n);

    // ---- head ----
    logits_kernel<<<(n * 32 + 255) / 256, 256>>>(hOut, Wout, bout, dout, n);
}